// round 1
// baseline (speedup 1.0000x reference)
#include <cuda_runtime.h>
#include <math.h>

#define EPS_BN 1e-5f
#define NB 16
#define NC 256
#define CQ 64
#define HH 64
#define WW 64
#define GHID 128
#define GIN 320

// Scratch (allocation-free: device globals). ~33.6 MB total.
__device__ float g_ef1[NB*CQ*HH*WW];
__device__ float g_ef2[NB*CQ*HH*WW];
__device__ float g_xpool[NB*NC];
__device__ float g_epool[NB*CQ];
__device__ float g_gate[NB*NC];

// ---------------------------------------------------------------------------
// conv3x3 (SAME, stride 1) + folded BN + ReLU.
// Block: 256 threads = 16 oc-groups (4 oc each) x 16 rows; tile = 16h x 8w.
// Per-thread register tile: 4 oc x 8 px. Sliding-window x reuse over kw.
// CIN=256 -> reads d_in x, writes g_ef1.  CIN=64 -> reads g_ef1, writes g_ef2.
// ---------------------------------------------------------------------------
template<int CIN>
__global__ __launch_bounds__(256)
void conv3x3_bn_relu(const float* __restrict__ xext,
                     const float* __restrict__ wg,
                     const float* __restrict__ cb,
                     const float* __restrict__ bg, const float* __restrict__ bb,
                     const float* __restrict__ bm, const float* __restrict__ bv)
{
    const int ICB = 8;
    __shared__ float sx[ICB*18*10];   // [ic][row 18][col 10]
    __shared__ float sw[64*73];       // [oc][ic*9+tap], padded row 73

    const float* __restrict__ xin = (CIN == NC) ? xext : (const float*)g_ef1;
    float* __restrict__ outp      = (CIN == NC) ? g_ef1 : g_ef2;

    const int bidx = blockIdx.z;
    const int h0 = blockIdx.y * 16;
    const int w0 = blockIdx.x * 8;
    const int tid = threadIdx.x;
    const int ocg = tid >> 4;         // 0..15
    const int row = tid & 15;         // 0..15
    const int oc0 = ocg * 4;

    float acc[4][8];
    #pragma unroll
    for (int j = 0; j < 4; j++)
        #pragma unroll
        for (int p = 0; p < 8; p++) acc[j][p] = 0.f;

    for (int icc = 0; icc < CIN; icc += ICB) {
        __syncthreads();
        // x tile with halo: rows h0-1..h0+16, cols w0-1..w0+8
        for (int i = tid; i < ICB*180; i += 256) {
            int ic = i / 180; int rem = i - ic*180;
            int r = rem / 10, c = rem - r*10;
            int gh = h0 + r - 1, gw = w0 + c - 1;
            float v = 0.f;
            if ((unsigned)gh < 64u && (unsigned)gw < 64u)
                v = xin[((bidx*CIN + icc + ic)*64 + gh)*64 + gw];
            sx[i] = v;
        }
        // weights: coalesced global read (72-float contiguous segments per oc)
        for (int i = tid; i < 64*72; i += 256) {
            int oc = i / 72, j = i - oc*72;
            int icl = j / 9, tap = j - icl*9;
            sw[oc*73 + j] = wg[(oc*CIN + icc + icl)*9 + tap];
        }
        __syncthreads();

        #pragma unroll 2
        for (int ic = 0; ic < ICB; ic++) {
            #pragma unroll
            for (int kh = 0; kh < 3; kh++) {
                float xv[10];
                #pragma unroll
                for (int cc = 0; cc < 10; cc++)
                    xv[cc] = sx[ic*180 + (row + kh)*10 + cc];
                #pragma unroll
                for (int kw = 0; kw < 3; kw++) {
                    #pragma unroll
                    for (int j = 0; j < 4; j++) {
                        float wv = sw[(oc0 + j)*73 + ic*9 + kh*3 + kw];
                        #pragma unroll
                        for (int p = 0; p < 8; p++)
                            acc[j][p] = fmaf(wv, xv[kw + p], acc[j][p]);
                    }
                }
            }
        }
    }

    // Epilogue: BN folded, y = raw*inv + ((cb - m)*inv + bb), then ReLU
    #pragma unroll
    for (int j = 0; j < 4; j++) {
        int oc = oc0 + j;
        float inv  = bg[oc] * rsqrtf(bv[oc] + EPS_BN);
        float beta = (cb[oc] - bm[oc]) * inv + bb[oc];
        #pragma unroll
        for (int p = 0; p < 8; p++) {
            float v = acc[j][p]*inv + beta;
            outp[((bidx*64 + oc)*64 + (h0 + row))*64 + (w0 + p)] = v > 0.f ? v : 0.f;
        }
    }
}

// ---------------------------------------------------------------------------
// Per-(b,c) spatial mean. which==0: x[16,256,.] -> g_xpool; which==1: g_ef2 -> g_epool
// ---------------------------------------------------------------------------
__global__ void pool_mean_kernel(const float* __restrict__ xext, int which)
{
    const float* src = (which == 0) ? xext : (const float*)g_ef2;
    float* dst       = (which == 0) ? g_xpool : g_epool;
    int bc = blockIdx.x, tid = threadIdx.x;
    const float* p = src + (size_t)bc * 4096;
    float s = 0.f;
    for (int i = tid; i < 4096; i += 256) s += p[i];
    __shared__ float red[8];
    #pragma unroll
    for (int o = 16; o > 0; o >>= 1) s += __shfl_down_sync(0xffffffffu, s, o);
    if ((tid & 31) == 0) red[tid >> 5] = s;
    __syncthreads();
    if (tid == 0) {
        float t = 0.f;
        #pragma unroll
        for (int i = 0; i < 8; i++) t += red[i];
        dst[bc] = t * (1.f / 4096.f);
    }
}

// ---------------------------------------------------------------------------
// Gate MLP: one block per batch sample. 128 threads.
// ---------------------------------------------------------------------------
__global__ void gate_kernel(const float* __restrict__ g1w, const float* __restrict__ g1b,
                            const float* __restrict__ gg,  const float* __restrict__ gb2,
                            const float* __restrict__ gm,  const float* __restrict__ gv,
                            const float* __restrict__ g2w, const float* __restrict__ g2b)
{
    __shared__ float sg[GIN];
    __shared__ float sh[GHID];
    int b = blockIdx.x, tid = threadIdx.x;
    for (int i = tid; i < NC; i += 128) sg[i] = g_xpool[b*NC + i];
    if (tid < CQ) sg[NC + tid] = g_epool[b*CQ + tid];
    __syncthreads();
    {
        int j = tid;  // 128 threads == GHID
        float a = g1b[j];
        for (int k = 0; k < GIN; k++) a = fmaf(sg[k], g1w[j*GIN + k], a);
        float inv = gg[j] * rsqrtf(gv[j] + EPS_BN);
        a = (a - gm[j]) * inv + gb2[j];
        sh[j] = a > 0.f ? a : 0.f;
    }
    __syncthreads();
    for (int c = tid; c < NC; c += 128) {
        float a = g2b[c];
        for (int k = 0; k < GHID; k++) a = fmaf(sh[k], g2w[c*GHID + k], a);
        g_gate[b*NC + c] = 1.f / (1.f + expf(-a));
    }
}

// ---------------------------------------------------------------------------
// Output: out = x + gate * (1x1 conv(g_ef2, out_w) + out_b)
// Block: one (b, h) row: 64 px x 256 oc, in 4 chunks of 64 oc.
// Threads 256 = 4 oc-groups (16 oc each) x 64 px.
// ---------------------------------------------------------------------------
__global__ __launch_bounds__(256)
void out_kernel(const float* __restrict__ x, const float* __restrict__ ow,
                const float* __restrict__ ob, float* __restrict__ out)
{
    __shared__ float sef[64*64];   // [ic][w]
    __shared__ float swt[64*64];   // [oc_local][ic]
    int h = blockIdx.x, b = blockIdx.y;
    int tid = threadIdx.x;
    int px = tid & 63, tg = tid >> 6;

    for (int i = tid; i < 64*64; i += 256) {
        int ic = i >> 6, wc = i & 63;
        sef[i] = g_ef2[((b*64 + ic)*64 + h)*64 + wc];
    }

    for (int occ = 0; occ < 4; occ++) {
        __syncthreads();
        for (int i = tid; i < 1024; i += 256) {
            int ocl = i >> 4, icq = i & 15;
            *(float4*)&swt[ocl*64 + icq*4] =
                *(const float4*)&ow[(occ*64 + ocl)*64 + icq*4];
        }
        __syncthreads();

        float acc[16];
        #pragma unroll
        for (int j = 0; j < 16; j++) acc[j] = 0.f;
        for (int ic = 0; ic < 64; ic += 4) {
            float x0 = sef[ic*64 + px],     x1 = sef[(ic+1)*64 + px];
            float x2 = sef[(ic+2)*64 + px], x3 = sef[(ic+3)*64 + px];
            #pragma unroll
            for (int j = 0; j < 16; j++) {
                const float4 wv = *(const float4*)&swt[(tg*16 + j)*64 + ic];
                acc[j] += wv.x*x0 + wv.y*x1 + wv.z*x2 + wv.w*x3;
            }
        }
        #pragma unroll
        for (int j = 0; j < 16; j++) {
            int oc = occ*64 + tg*16 + j;
            size_t idx = (((size_t)b*NC + oc)*64 + h)*64 + px;
            float v = acc[j] + ob[oc];
            out[idx] = x[idx] + g_gate[b*NC + oc] * v;
        }
    }
}

// ---------------------------------------------------------------------------
extern "C" void kernel_launch(void* const* d_in, const int* in_sizes, int n_in,
                              void* d_out, int out_size)
{
    const float* x     = (const float*)d_in[0];
    const float* ec1_w = (const float*)d_in[1];
    const float* ec1_b = (const float*)d_in[2];
    const float* bn1_g = (const float*)d_in[3];
    const float* bn1_b = (const float*)d_in[4];
    const float* bn1_m = (const float*)d_in[5];
    const float* bn1_v = (const float*)d_in[6];
    const float* ec2_w = (const float*)d_in[7];
    const float* ec2_b = (const float*)d_in[8];
    const float* bn2_g = (const float*)d_in[9];
    const float* bn2_b = (const float*)d_in[10];
    const float* bn2_m = (const float*)d_in[11];
    const float* bn2_v = (const float*)d_in[12];
    const float* g1_w  = (const float*)d_in[13];
    const float* g1_b  = (const float*)d_in[14];
    const float* gbn_g = (const float*)d_in[15];
    const float* gbn_b = (const float*)d_in[16];
    const float* gbn_m = (const float*)d_in[17];
    const float* gbn_v = (const float*)d_in[18];
    const float* g2_w  = (const float*)d_in[19];
    const float* g2_b  = (const float*)d_in[20];
    const float* out_w = (const float*)d_in[21];
    const float* out_b = (const float*)d_in[22];
    float* out = (float*)d_out;

    dim3 cgrid(8, 4, 16);   // 8 w-tiles x 4 h-tiles x 16 batches

    conv3x3_bn_relu<NC><<<cgrid, 256>>>(x, ec1_w, ec1_b, bn1_g, bn1_b, bn1_m, bn1_v);
    conv3x3_bn_relu<CQ><<<cgrid, 256>>>(x, ec2_w, ec2_b, bn2_g, bn2_b, bn2_m, bn2_v);

    pool_mean_kernel<<<NB*NC, 256>>>(x, 0);   // x_pool  (independent of convs)
    pool_mean_kernel<<<NB*CQ, 256>>>(x, 1);   // e_pool  (needs g_ef2)

    gate_kernel<<<NB, 128>>>(g1_w, g1_b, gbn_g, gbn_b, gbn_m, gbn_v, g2_w, g2_b);

    out_kernel<<<dim3(64, NB), 256>>>(x, out_w, out_b, out);
}

// round 5
// speedup vs baseline: 2.4269x; 2.4269x over previous
#include <cuda_runtime.h>
#include <math.h>
#include <stdint.h>

#define EPS_BN 1e-5f
#define NB 16
#define NC 256
#define CQ 64
#define GHID 128
#define GIN 320

// ---------------------------------------------------------------------------
// Scratch (allocation-free device globals)
// ---------------------------------------------------------------------------
__device__ float g_ef1[NB*CQ*64*64];
__device__ float g_ef2[NB*CQ*64*64];
__device__ float g_xpool[NB*NC];
__device__ float g_epool[NB*CQ];
__device__ float g_gate[NB*NC];
__device__ float g_w1t[9*64*256];   // [tap][oc][ic]
__device__ float g_w2t[9*64*64];    // [tap][oc][ic]

__device__ __forceinline__ uint32_t f2tf(float f){
    uint32_t r; asm("cvt.rna.tf32.f32 %0, %1;" : "=r"(r) : "f"(f)); return r;
}
__device__ __forceinline__ float tfbits(float f){ return __uint_as_float(f2tf(f)); }

// m16n8k8 tf32 MMA, fp32 accum. A row-major, B col-major.
__device__ __forceinline__ void mma8(float* d, const uint32_t* a, const uint32_t* b){
    asm volatile("mma.sync.aligned.m16n8k8.row.col.f32.tf32.tf32.f32 "
        "{%0,%1,%2,%3}, {%4,%5,%6,%7}, {%8,%9}, {%0,%1,%2,%3};"
        : "+f"(d[0]), "+f"(d[1]), "+f"(d[2]), "+f"(d[3])
        : "r"(a[0]), "r"(a[1]), "r"(a[2]), "r"(a[3]), "r"(b[0]), "r"(b[1]));
}

// ---------------------------------------------------------------------------
// Weight transform: [oc][ic][3][3] -> [tap][oc][ic]
// ---------------------------------------------------------------------------
__global__ void wtrans_kernel(const float* __restrict__ w1, const float* __restrict__ w2)
{
    int i = blockIdx.x * 256 + threadIdx.x;
    if (i < 9*64*256) {
        int tap = i / (64*256); int rem = i - tap*(64*256);
        int oc = rem >> 8, ic = rem & 255;
        g_w1t[i] = w1[(oc*256 + ic)*9 + tap];
    }
    int j = i - 9*64*256;
    if (j >= 0 && j < 9*64*64) {
        int tap = j / (64*64); int rem = j - tap*(64*64);
        int oc = rem >> 6, ic = rem & 63;
        g_w2t[j] = w2[(oc*64 + ic)*9 + tap];
    }
}

// ---------------------------------------------------------------------------
// conv3x3 + BN + ReLU via mma.sync tf32 tap-split implicit GEMM.
// Block: 128 px (2 rows x 64 w) x 64 oc. 4 warps, warp tile 64px x 32oc.
// Grid: (32 rowpairs, 16 batches). Dynamic SMEM: 43520 B (< 48K default).
// SMEM floats: slab[ic32][rs4][ws66] @0 (8448), Bs[oc64][ic36] @8448 (2304),
//              sinv @10752, sbeta @10816. Epilogue sD[oc64][px132] reuses slab.
// ---------------------------------------------------------------------------
template<int CIN>
__global__ __launch_bounds__(128)
void conv_mma(const float* __restrict__ xg,
              const float* __restrict__ cb,
              const float* __restrict__ bg, const float* __restrict__ bb,
              const float* __restrict__ bm, const float* __restrict__ bv)
{
    extern __shared__ float sm[];
    float* slab  = sm;            // 8448
    float* Bs    = sm + 8448;     // 2304
    float* sinv  = sm + 10752;    // 64
    float* sbeta = sm + 10816;    // 64

    const float* __restrict__ xin = (CIN == NC) ? xg : (const float*)g_ef1;
    float* __restrict__ outp      = (CIN == NC) ? g_ef1 : g_ef2;
    const float* __restrict__ wt  = (CIN == NC) ? (const float*)g_w1t : (const float*)g_w2t;

    const int tid = threadIdx.x, lane = tid & 31, wid = tid >> 5;
    const int warpM = wid & 1, warpN = wid >> 1;     // M: 2x64px, N: 2x32oc
    const int r = lane >> 2, c = lane & 3;
    const int b = blockIdx.y, h0 = blockIdx.x * 2;

    if (tid < 64) {
        float inv = bg[tid] * rsqrtf(bv[tid] + EPS_BN);
        sinv[tid]  = inv;
        sbeta[tid] = (cb[tid] - bm[tid]) * inv + bb[tid];
    }

    float d[4][4][4];
    #pragma unroll
    for (int mt = 0; mt < 4; mt++)
        #pragma unroll
        for (int nt = 0; nt < 4; nt++)
            #pragma unroll
            for (int q = 0; q < 4; q++) d[mt][nt][q] = 0.f;

    const int CH = CIN / 32;
    for (int ch = 0; ch < CH; ch++) {
        __syncthreads();
        // slab: input rows h0-1..h0+2, cols -1..64, tf32-rounded
        const float* xsrc = xin + ((size_t)(b*CIN + ch*32)) * 4096;
        for (int i = tid; i < 8448; i += 128) {
            int ic = i / 264; int rem = i - ic*264;
            int rs = rem / 66, ws = rem - rs*66;
            int gr = h0 - 1 + rs, gw = ws - 1;
            float v = 0.f;
            if ((unsigned)gr < 64u && (unsigned)gw < 64u)
                v = xsrc[ic*4096 + gr*64 + gw];
            slab[i] = tfbits(v);
        }

        for (int tap = 0; tap < 9; tap++) {
            __syncthreads();
            // stage B: [oc][ic] pad 36
            {
                const float* wsrc = wt + ((size_t)tap*64)*CIN + ch*32;
                for (int i = tid; i < 2048; i += 128) {
                    int oc = i >> 5, ic = i & 31;
                    Bs[oc*36 + ic] = tfbits(wsrc[oc*CIN + ic]);
                }
            }
            __syncthreads();
            const int kh = tap / 3, kw = tap - kh*3;
            const int rowoff = (warpM + kh)*66 + kw;

            #pragma unroll
            for (int k8 = 0; k8 < 4; k8++) {
                const int ic0 = k8*8 + c;
                uint32_t a[4][4];
                #pragma unroll
                for (int mt = 0; mt < 4; mt++) {
                    int ws = mt*16 + r;
                    a[mt][0] = __float_as_uint(slab[ic0*264 + rowoff + ws]);
                    a[mt][1] = __float_as_uint(slab[ic0*264 + rowoff + ws + 8]);
                    a[mt][2] = __float_as_uint(slab[(ic0+4)*264 + rowoff + ws]);
                    a[mt][3] = __float_as_uint(slab[(ic0+4)*264 + rowoff + ws + 8]);
                }
                uint32_t bf[4][2];
                #pragma unroll
                for (int nt = 0; nt < 4; nt++) {
                    int oc = warpN*32 + nt*8 + r;
                    bf[nt][0] = __float_as_uint(Bs[oc*36 + ic0]);
                    bf[nt][1] = __float_as_uint(Bs[oc*36 + ic0 + 4]);
                }
                #pragma unroll
                for (int mt = 0; mt < 4; mt++)
                    #pragma unroll
                    for (int nt = 0; nt < 4; nt++)
                        mma8(d[mt][nt], a[mt], bf[nt]);
            }
        }
    }

    // Epilogue: BN+ReLU, transpose through smem (reuse slab), coalesced store
    __syncthreads();
    float* sD = slab;   // [oc][px] pad 132 -> 64*132 = 8448 floats
    #pragma unroll
    for (int mt = 0; mt < 4; mt++) {
        int px0 = warpM*64 + mt*16 + r;
        #pragma unroll
        for (int nt = 0; nt < 4; nt++) {
            int oc0 = warpN*32 + nt*8 + c*2;
            float i0 = sinv[oc0],   b0 = sbeta[oc0];
            float i1 = sinv[oc0+1], b1 = sbeta[oc0+1];
            float v0 = d[mt][nt][0]*i0 + b0;
            float v1 = d[mt][nt][1]*i1 + b1;
            float v2 = d[mt][nt][2]*i0 + b0;
            float v3 = d[mt][nt][3]*i1 + b1;
            sD[oc0*132 + px0]           = v0 > 0.f ? v0 : 0.f;
            sD[(oc0+1)*132 + px0]       = v1 > 0.f ? v1 : 0.f;
            sD[oc0*132 + px0 + 8]       = v2 > 0.f ? v2 : 0.f;
            sD[(oc0+1)*132 + px0 + 8]   = v3 > 0.f ? v3 : 0.f;
        }
    }
    __syncthreads();
    for (int i = tid; i < 8192; i += 128) {
        int oc = i >> 7, px = i & 127;
        int rs = px >> 6, w = px & 63;
        outp[(((size_t)b*64 + oc)*64 + h0 + rs)*64 + w] = sD[oc*132 + px];
    }
}

// ---------------------------------------------------------------------------
// Output 1x1 GEMM + gated residual: out = x + gate*(ef2 @ out_w^T + ob)
// Block: 64 px (one h-row) x 64 oc. 4 warps (N), warp tile 64px x 16oc.
// Grid: (64 h, 4 oc-chunks, 16 b). Dynamic SMEM: 36352 B (< 48K default).
// SMEM floats: sA[ic64][w72] @0 (4608), sB[oc64][ic68] @4608 (4352),
//              sgate @8960, sob @9024. sD[oc64][w68] reuses @0.
// ---------------------------------------------------------------------------
__global__ __launch_bounds__(128)
void out_mma(const float* __restrict__ x, const float* __restrict__ ow,
             const float* __restrict__ ob, float* __restrict__ out)
{
    extern __shared__ float sm[];
    float* sA    = sm;           // 4608
    float* sB    = sm + 4608;    // 4352
    float* sgate = sm + 8960;    // 64
    float* sob   = sm + 9024;    // 64

    const int tid = threadIdx.x, lane = tid & 31, warpN = tid >> 5;
    const int r = lane >> 2, c = lane & 3;
    const int h = blockIdx.x, och = blockIdx.y, b = blockIdx.z;
    const int ocb = och * 64;

    if (tid < 64) {
        sgate[tid] = g_gate[b*256 + ocb + tid];
        sob[tid]   = ob[ocb + tid];
    }
    // A: [ic64][w] from ef2 (coalesced over w)
    for (int i = tid; i < 4096; i += 128) {
        int ic = i >> 6, w = i & 63;
        sA[ic*72 + w] = tfbits(g_ef2[(((size_t)b*64 + ic)*64 + h)*64 + w]);
    }
    // B: [oc64][ic64] from out_w (coalesced over ic)
    for (int i = tid; i < 4096; i += 128) {
        int oc = i >> 6, ic = i & 63;
        sB[oc*68 + ic] = tfbits(ow[(ocb + oc)*64 + ic]);
    }
    __syncthreads();

    float d[4][2][4];
    #pragma unroll
    for (int mt = 0; mt < 4; mt++)
        #pragma unroll
        for (int nt = 0; nt < 2; nt++)
            #pragma unroll
            for (int q = 0; q < 4; q++) d[mt][nt][q] = 0.f;

    #pragma unroll
    for (int k8 = 0; k8 < 8; k8++) {
        const int ic0 = k8*8 + c;
        uint32_t a[4][4];
        #pragma unroll
        for (int mt = 0; mt < 4; mt++) {
            int ws = mt*16 + r;
            a[mt][0] = __float_as_uint(sA[ic0*72 + ws]);
            a[mt][1] = __float_as_uint(sA[ic0*72 + ws + 8]);
            a[mt][2] = __float_as_uint(sA[(ic0+4)*72 + ws]);
            a[mt][3] = __float_as_uint(sA[(ic0+4)*72 + ws + 8]);
        }
        uint32_t bf[2][2];
        #pragma unroll
        for (int nt = 0; nt < 2; nt++) {
            int oc = warpN*16 + nt*8 + r;
            bf[nt][0] = __float_as_uint(sB[oc*68 + ic0]);
            bf[nt][1] = __float_as_uint(sB[oc*68 + ic0 + 4]);
        }
        #pragma unroll
        for (int mt = 0; mt < 4; mt++)
            #pragma unroll
            for (int nt = 0; nt < 2; nt++)
                mma8(d[mt][nt], a[mt], bf[nt]);
    }

    __syncthreads();
    float* sD = sm;   // [oc64][w68] = 4352 floats (fits in sA region+)
    #pragma unroll
    for (int mt = 0; mt < 4; mt++) {
        int px0 = mt*16 + r;
        #pragma unroll
        for (int nt = 0; nt < 2; nt++) {
            int oc0 = warpN*16 + nt*8 + c*2;
            sD[oc0*68 + px0]         = d[mt][nt][0];
            sD[(oc0+1)*68 + px0]     = d[mt][nt][1];
            sD[oc0*68 + px0 + 8]     = d[mt][nt][2];
            sD[(oc0+1)*68 + px0 + 8] = d[mt][nt][3];
        }
    }
    __syncthreads();
    for (int i = tid; i < 4096; i += 128) {
        int oc = i >> 6, w = i & 63;
        size_t idx = (((size_t)b*256 + ocb + oc)*64 + h)*64 + w;
        out[idx] = x[idx] + sgate[oc] * (sD[oc*68 + w] + sob[oc]);
    }
}

// ---------------------------------------------------------------------------
// Per-(b,c) spatial mean
// ---------------------------------------------------------------------------
__global__ void pool_mean_kernel(const float* __restrict__ xext, int which)
{
    const float* src = (which == 0) ? xext : (const float*)g_ef2;
    float* dst       = (which == 0) ? g_xpool : g_epool;
    int bc = blockIdx.x, tid = threadIdx.x;
    const float* p = src + (size_t)bc * 4096;
    float s = 0.f;
    for (int i = tid; i < 4096; i += 256) s += p[i];
    __shared__ float red[8];
    #pragma unroll
    for (int o = 16; o > 0; o >>= 1) s += __shfl_down_sync(0xffffffffu, s, o);
    if ((tid & 31) == 0) red[tid >> 5] = s;
    __syncthreads();
    if (tid == 0) {
        float t = 0.f;
        #pragma unroll
        for (int i = 0; i < 8; i++) t += red[i];
        dst[bc] = t * (1.f / 4096.f);
    }
}

// ---------------------------------------------------------------------------
// Gate MLP
// ---------------------------------------------------------------------------
__global__ void gate_kernel(const float* __restrict__ g1w, const float* __restrict__ g1b,
                            const float* __restrict__ gg,  const float* __restrict__ gb2,
                            const float* __restrict__ gm,  const float* __restrict__ gv,
                            const float* __restrict__ g2w, const float* __restrict__ g2b)
{
    __shared__ float sg[GIN];
    __shared__ float sh[GHID];
    int b = blockIdx.x, tid = threadIdx.x;
    for (int i = tid; i < NC; i += 128) sg[i] = g_xpool[b*NC + i];
    if (tid < CQ) sg[NC + tid] = g_epool[b*CQ + tid];
    __syncthreads();
    {
        int j = tid;
        float a = g1b[j];
        for (int k = 0; k < GIN; k++) a = fmaf(sg[k], g1w[j*GIN + k], a);
        float inv = gg[j] * rsqrtf(gv[j] + EPS_BN);
        a = (a - gm[j]) * inv + gb2[j];
        sh[j] = a > 0.f ? a : 0.f;
    }
    __syncthreads();
    for (int cc = tid; cc < NC; cc += 128) {
        float a = g2b[cc];
        for (int k = 0; k < GHID; k++) a = fmaf(sh[k], g2w[cc*GHID + k], a);
        g_gate[b*NC + cc] = 1.f / (1.f + expf(-a));
    }
}

// ---------------------------------------------------------------------------
extern "C" void kernel_launch(void* const* d_in, const int* in_sizes, int n_in,
                              void* d_out, int out_size)
{
    const float* x     = (const float*)d_in[0];
    const float* ec1_w = (const float*)d_in[1];
    const float* ec1_b = (const float*)d_in[2];
    const float* bn1_g = (const float*)d_in[3];
    const float* bn1_b = (const float*)d_in[4];
    const float* bn1_m = (const float*)d_in[5];
    const float* bn1_v = (const float*)d_in[6];
    const float* ec2_w = (const float*)d_in[7];
    const float* ec2_b = (const float*)d_in[8];
    const float* bn2_g = (const float*)d_in[9];
    const float* bn2_b = (const float*)d_in[10];
    const float* bn2_m = (const float*)d_in[11];
    const float* bn2_v = (const float*)d_in[12];
    const float* g1_w  = (const float*)d_in[13];
    const float* g1_b  = (const float*)d_in[14];
    const float* gbn_g = (const float*)d_in[15];
    const float* gbn_b = (const float*)d_in[16];
    const float* gbn_m = (const float*)d_in[17];
    const float* gbn_v = (const float*)d_in[18];
    const float* g2_w  = (const float*)d_in[19];
    const float* g2_b  = (const float*)d_in[20];
    const float* out_w = (const float*)d_in[21];
    const float* out_b = (const float*)d_in[22];
    float* out = (float*)d_out;

    const int CONV_SMEM = 10880 * 4;   // 43520 B  (< 48KB, no opt-in needed)
    const int OUT_SMEM  = 9088 * 4;    // 36352 B  (< 48KB, no opt-in needed)

    wtrans_kernel<<<720, 256>>>(ec1_w, ec2_w);

    conv_mma<NC><<<dim3(32, 16), 128, CONV_SMEM>>>(x, ec1_b, bn1_g, bn1_b, bn1_m, bn1_v);
    conv_mma<CQ><<<dim3(32, 16), 128, CONV_SMEM>>>(x, ec2_b, bn2_g, bn2_b, bn2_m, bn2_v);

    pool_mean_kernel<<<NB*NC, 256>>>(x, 0);
    pool_mean_kernel<<<NB*CQ, 256>>>(x, 1);

    gate_kernel<<<NB, 128>>>(g1_w, g1_b, gbn_g, gbn_b, gbn_m, gbn_v, g2_w, g2_b);

    out_mma<<<dim3(64, 4, NB), 128, OUT_SMEM>>>(x, out_w, out_b, out);
}

// round 8
// speedup vs baseline: 3.8316x; 1.5788x over previous
#include <cuda_runtime.h>
#include <math.h>
#include <stdint.h>

#define EPS_BN 1e-5f
#define NB 16
#define NC 256
#define CQ 64
#define GHID 128
#define GIN 320

// ---------------------------------------------------------------------------
// Scratch (allocation-free device globals)
// ---------------------------------------------------------------------------
__device__ float g_ef1[NB*CQ*64*64];
__device__ float g_ef2[NB*CQ*64*64];
__device__ float g_xpool[NB*NC];
__device__ float g_epool[NB*CQ];
__device__ float g_gate[NB*NC];
__device__ float g_w1t[9*64*256];   // [tap][oc][ic], tf32-rounded
__device__ float g_w2t[9*64*64];    // [tap][oc][ic], tf32-rounded

__device__ __forceinline__ float tf_rna(float f){
    uint32_t r; asm("cvt.rna.tf32.f32 %0, %1;" : "=r"(r) : "f"(f));
    return __uint_as_float(r);
}

// m16n8k8 tf32 MMA, fp32 accum. A row-major, B col-major.
// Operands passed as raw fp32 bit containers (HW uses tf32 subset -> truncation).
__device__ __forceinline__ void mma8(float* d, const uint32_t* a, const uint32_t* b){
    asm volatile("mma.sync.aligned.m16n8k8.row.col.f32.tf32.tf32.f32 "
        "{%0,%1,%2,%3}, {%4,%5,%6,%7}, {%8,%9}, {%0,%1,%2,%3};"
        : "+f"(d[0]), "+f"(d[1]), "+f"(d[2]), "+f"(d[3])
        : "r"(a[0]), "r"(a[1]), "r"(a[2]), "r"(a[3]), "r"(b[0]), "r"(b[1]));
}

// ---------------------------------------------------------------------------
// Weight transform: [oc][ic][3][3] -> [tap][oc][ic], rna-rounded to tf32
// ---------------------------------------------------------------------------
__global__ void wtrans_kernel(const float* __restrict__ w1, const float* __restrict__ w2)
{
    int i = blockIdx.x * 256 + threadIdx.x;
    if (i < 9*64*256) {
        int tap = i / (64*256); int rem = i - tap*(64*256);
        int oc = rem >> 8, ic = rem & 255;
        g_w1t[i] = tf_rna(w1[(oc*256 + ic)*9 + tap]);
    }
    int j = i - 9*64*256;
    if (j >= 0 && j < 9*64*64) {
        int tap = j / (64*64); int rem = j - tap*(64*64);
        int oc = rem >> 6, ic = rem & 63;
        g_w2t[j] = tf_rna(w2[(oc*64 + ic)*9 + tap]);
    }
}

// ---------------------------------------------------------------------------
// conv3x3 + BN + ReLU via mma.sync tf32 tap-split implicit GEMM.
// Block: 128 px (2 rows x 64 w) x 64 oc. 4 warps, warp tile 64px x 32oc.
// Grid: (32 rowpairs, 16 batches). Dynamic SMEM: 43520 B.
// SMEM floats: slab[ic32][rs4][ws66] @0 (8448), Bs[oc64][ic36] @8448 (2304),
//              sinv @10752, sbeta @10816. Epilogue sD[oc64][px132] reuses slab.
// ---------------------------------------------------------------------------
template<int CIN>
__global__ __launch_bounds__(128)
void conv_mma(const float* __restrict__ xg,
              const float* __restrict__ cb,
              const float* __restrict__ bg, const float* __restrict__ bb,
              const float* __restrict__ bm, const float* __restrict__ bv)
{
    extern __shared__ float sm[];
    float* slab  = sm;            // 8448
    float* Bs    = sm + 8448;     // 2304
    float* sinv  = sm + 10752;    // 64
    float* sbeta = sm + 10816;    // 64

    const float* __restrict__ xin = (CIN == NC) ? xg : (const float*)g_ef1;
    float* __restrict__ outp      = (CIN == NC) ? g_ef1 : g_ef2;
    const float* __restrict__ wt  = (CIN == NC) ? (const float*)g_w1t : (const float*)g_w2t;

    const int tid = threadIdx.x, lane = tid & 31, wid = tid >> 5;
    const int warpM = wid & 1, warpN = wid >> 1;     // M: 2x64px, N: 2x32oc
    const int r = lane >> 2, c = lane & 3;
    const int b = blockIdx.y, h0 = blockIdx.x * 2;

    if (tid < 64) {
        float inv = bg[tid] * rsqrtf(bv[tid] + EPS_BN);
        sinv[tid]  = inv;
        sbeta[tid] = (cb[tid] - bm[tid]) * inv + bb[tid];
    }
    // halo columns (ws=0, ws=65) are always out-of-image -> zero once
    for (int i = tid; i < 256; i += 128) {      // 32 ic * 4 rs * 2
        int ic = i >> 3, rem = i & 7, rs = rem >> 1, e = rem & 1;
        slab[ic*264 + rs*66 + e*65] = 0.f;
    }

    float d[4][4][4];
    #pragma unroll
    for (int mt = 0; mt < 4; mt++)
        #pragma unroll
        for (int nt = 0; nt < 4; nt++)
            #pragma unroll
            for (int q = 0; q < 4; q++) d[mt][nt][q] = 0.f;

    const int CH = CIN / 32;
    for (int ch = 0; ch < CH; ch++) {
        __syncthreads();   // prior tap's readers done with slab
        // interior fill: division-free, float4 loads (16 per thread)
        const float* xsrc = xin + ((size_t)(b*CIN + ch*32)) * 4096;
        #pragma unroll 4
        for (int i = tid; i < 2048; i += 128) {
            int ic = i >> 6, rem = i & 63, rs = rem >> 4, q = rem & 15;
            int gr = h0 - 1 + rs;
            float4 v = make_float4(0.f, 0.f, 0.f, 0.f);
            if ((unsigned)gr < 64u)
                v = *(const float4*)(xsrc + ic*4096 + gr*64 + q*4);
            float* dst = slab + ic*264 + rs*66 + 1 + q*4;
            dst[0] = v.x; dst[1] = v.y; dst[2] = v.z; dst[3] = v.w;
        }

        for (int tap = 0; tap < 9; tap++) {
            if (tap > 0) __syncthreads();   // readers of Bs done
            // stage B (pre-rounded tf32): 4 float4 per thread
            {
                const float* wsrc = wt + ((size_t)tap*64)*CIN + ch*32;
                #pragma unroll
                for (int i = tid; i < 512; i += 128) {
                    int oc = i >> 3, icq = i & 7;
                    *(float4*)(Bs + oc*36 + icq*4) =
                        *(const float4*)(wsrc + oc*CIN + icq*4);
                }
            }
            __syncthreads();
            const int kh = tap / 3, kw = tap - kh*3;
            const int rowoff = (warpM + kh)*66 + kw;

            #pragma unroll
            for (int k8 = 0; k8 < 4; k8++) {
                const int ic0 = k8*8 + c;
                uint32_t a[4][4];
                #pragma unroll
                for (int mt = 0; mt < 4; mt++) {
                    int ws = mt*16 + r;
                    a[mt][0] = __float_as_uint(slab[ic0*264 + rowoff + ws]);
                    a[mt][1] = __float_as_uint(slab[ic0*264 + rowoff + ws + 8]);
                    a[mt][2] = __float_as_uint(slab[(ic0+4)*264 + rowoff + ws]);
                    a[mt][3] = __float_as_uint(slab[(ic0+4)*264 + rowoff + ws + 8]);
                }
                uint32_t bf[4][2];
                #pragma unroll
                for (int nt = 0; nt < 4; nt++) {
                    int oc = warpN*32 + nt*8 + r;
                    bf[nt][0] = __float_as_uint(Bs[oc*36 + ic0]);
                    bf[nt][1] = __float_as_uint(Bs[oc*36 + ic0 + 4]);
                }
                #pragma unroll
                for (int mt = 0; mt < 4; mt++)
                    #pragma unroll
                    for (int nt = 0; nt < 4; nt++)
                        mma8(d[mt][nt], a[mt], bf[nt]);
            }
        }
    }

    // Epilogue: BN+ReLU, transpose through smem (reuse slab), float4 store
    __syncthreads();
    float* sD = slab;   // [oc][px] pad 132 -> 64*132 = 8448 floats
    #pragma unroll
    for (int mt = 0; mt < 4; mt++) {
        int px0 = warpM*64 + mt*16 + r;
        #pragma unroll
        for (int nt = 0; nt < 4; nt++) {
            int oc0 = warpN*32 + nt*8 + c*2;
            float i0 = sinv[oc0],   b0 = sbeta[oc0];
            float i1 = sinv[oc0+1], b1 = sbeta[oc0+1];
            float v0 = d[mt][nt][0]*i0 + b0;
            float v1 = d[mt][nt][1]*i1 + b1;
            float v2 = d[mt][nt][2]*i0 + b0;
            float v3 = d[mt][nt][3]*i1 + b1;
            sD[oc0*132 + px0]           = v0 > 0.f ? v0 : 0.f;
            sD[(oc0+1)*132 + px0]       = v1 > 0.f ? v1 : 0.f;
            sD[oc0*132 + px0 + 8]       = v2 > 0.f ? v2 : 0.f;
            sD[(oc0+1)*132 + px0 + 8]   = v3 > 0.f ? v3 : 0.f;
        }
    }
    __syncthreads();
    #pragma unroll 4
    for (int i = tid; i < 2048; i += 128) {
        int oc = i >> 5, pxq = i & 31;
        int px = pxq * 4;
        int rs = px >> 6, w = px & 63;
        float4 v = *(const float4*)(sD + oc*132 + px);
        *(float4*)(outp + (((size_t)b*64 + oc)*64 + h0 + rs)*64 + w) = v;
    }
}

// ---------------------------------------------------------------------------
// Output 1x1 GEMM + gated residual: out = x + gate*(ef2 @ out_w^T + ob)
// Block: 64 px (one h-row) x 64 oc. 4 warps (N), warp tile 64px x 16oc.
// Grid: (64 h, 4 oc-chunks, 16 b). Dynamic SMEM: 36352 B.
// ---------------------------------------------------------------------------
__global__ __launch_bounds__(128)
void out_mma(const float* __restrict__ x, const float* __restrict__ ow,
             const float* __restrict__ ob, float* __restrict__ out)
{
    extern __shared__ float sm[];
    float* sA    = sm;           // 4608  [ic64][w72]
    float* sB    = sm + 4608;    // 4352  [oc64][ic68]
    float* sgate = sm + 8960;    // 64
    float* sob   = sm + 9024;    // 64

    const int tid = threadIdx.x, lane = tid & 31, warpN = tid >> 5;
    const int r = lane >> 2, c = lane & 3;
    const int h = blockIdx.x, och = blockIdx.y, b = blockIdx.z;
    const int ocb = och * 64;

    if (tid < 64) {
        sgate[tid] = g_gate[b*256 + ocb + tid];
        sob[tid]   = ob[ocb + tid];
    }
    // A: [ic64][w] from ef2, float4
    #pragma unroll
    for (int i = tid; i < 1024; i += 128) {
        int ic = i >> 4, wq = i & 15;
        *(float4*)(sA + ic*72 + wq*4) =
            *(const float4*)(g_ef2 + (((size_t)b*64 + ic)*64 + h)*64 + wq*4);
    }
    // B: [oc64][ic64] from out_w, float4 (tf32 via HW truncation)
    #pragma unroll
    for (int i = tid; i < 1024; i += 128) {
        int oc = i >> 4, icq = i & 15;
        *(float4*)(sB + oc*68 + icq*4) =
            *(const float4*)(ow + (ocb + oc)*64 + icq*4);
    }
    __syncthreads();

    float d[4][2][4];
    #pragma unroll
    for (int mt = 0; mt < 4; mt++)
        #pragma unroll
        for (int nt = 0; nt < 2; nt++)
            #pragma unroll
            for (int q = 0; q < 4; q++) d[mt][nt][q] = 0.f;

    #pragma unroll
    for (int k8 = 0; k8 < 8; k8++) {
        const int ic0 = k8*8 + c;
        uint32_t a[4][4];
        #pragma unroll
        for (int mt = 0; mt < 4; mt++) {
            int ws = mt*16 + r;
            a[mt][0] = __float_as_uint(sA[ic0*72 + ws]);
            a[mt][1] = __float_as_uint(sA[ic0*72 + ws + 8]);
            a[mt][2] = __float_as_uint(sA[(ic0+4)*72 + ws]);
            a[mt][3] = __float_as_uint(sA[(ic0+4)*72 + ws + 8]);
        }
        uint32_t bf[2][2];
        #pragma unroll
        for (int nt = 0; nt < 2; nt++) {
            int oc = warpN*16 + nt*8 + r;
            bf[nt][0] = __float_as_uint(sB[oc*68 + ic0]);
            bf[nt][1] = __float_as_uint(sB[oc*68 + ic0 + 4]);
        }
        #pragma unroll
        for (int mt = 0; mt < 4; mt++)
            #pragma unroll
            for (int nt = 0; nt < 2; nt++)
                mma8(d[mt][nt], a[mt], bf[nt]);
    }

    __syncthreads();
    float* sD = sm;   // [oc64][w68] = 4352 floats
    #pragma unroll
    for (int mt = 0; mt < 4; mt++) {
        int px0 = mt*16 + r;
        #pragma unroll
        for (int nt = 0; nt < 2; nt++) {
            int oc0 = warpN*16 + nt*8 + c*2;
            sD[oc0*68 + px0]         = d[mt][nt][0];
            sD[(oc0+1)*68 + px0]     = d[mt][nt][1];
            sD[oc0*68 + px0 + 8]     = d[mt][nt][2];
            sD[(oc0+1)*68 + px0 + 8] = d[mt][nt][3];
        }
    }
    __syncthreads();
    #pragma unroll
    for (int i = tid; i < 1024; i += 128) {
        int oc = i >> 4, wq = i & 15;
        size_t idx = (((size_t)b*256 + ocb + oc)*64 + h)*64 + wq*4;
        float4 xv = *(const float4*)(x + idx);
        float4 dv = *(const float4*)(sD + oc*68 + wq*4);
        float g = sgate[oc], o = sob[oc];
        float4 rv;
        rv.x = xv.x + g*(dv.x + o);
        rv.y = xv.y + g*(dv.y + o);
        rv.z = xv.z + g*(dv.z + o);
        rv.w = xv.w + g*(dv.w + o);
        *(float4*)(out + idx) = rv;
    }
}

// ---------------------------------------------------------------------------
// Per-(b,c) spatial mean: float4 + deep MLP (8 independent loads/thread)
// ---------------------------------------------------------------------------
__global__ __launch_bounds__(128)
void pool_mean_kernel(const float* __restrict__ xext, int which)
{
    const float* src = (which == 0) ? xext : (const float*)g_ef2;
    float* dst       = (which == 0) ? g_xpool : g_epool;
    int bc = blockIdx.x, tid = threadIdx.x;
    const float4* p = (const float4*)(src + (size_t)bc * 4096);
    float4 acc[8];
    #pragma unroll
    for (int j = 0; j < 8; j++) acc[j] = p[tid + j*128];
    float s = 0.f;
    #pragma unroll
    for (int j = 0; j < 8; j++) s += (acc[j].x + acc[j].y) + (acc[j].z + acc[j].w);
    __shared__ float red[4];
    #pragma unroll
    for (int o = 16; o > 0; o >>= 1) s += __shfl_down_sync(0xffffffffu, s, o);
    if ((tid & 31) == 0) red[tid >> 5] = s;
    __syncthreads();
    if (tid == 0)
        dst[bc] = (red[0] + red[1] + red[2] + red[3]) * (1.f / 4096.f);
}

// ---------------------------------------------------------------------------
// Gate MLP
// ---------------------------------------------------------------------------
__global__ void gate_kernel(const float* __restrict__ g1w, const float* __restrict__ g1b,
                            const float* __restrict__ gg,  const float* __restrict__ gb2,
                            const float* __restrict__ gm,  const float* __restrict__ gv,
                            const float* __restrict__ g2w, const float* __restrict__ g2b)
{
    __shared__ float sg[GIN];
    __shared__ float sh[GHID];
    int b = blockIdx.x, tid = threadIdx.x;
    for (int i = tid; i < NC; i += 128) sg[i] = g_xpool[b*NC + i];
    if (tid < CQ) sg[NC + tid] = g_epool[b*CQ + tid];
    __syncthreads();
    {
        int j = tid;
        float a = g1b[j];
        for (int k = 0; k < GIN; k++) a = fmaf(sg[k], g1w[j*GIN + k], a);
        float inv = gg[j] * rsqrtf(gv[j] + EPS_BN);
        a = (a - gm[j]) * inv + gb2[j];
        sh[j] = a > 0.f ? a : 0.f;
    }
    __syncthreads();
    for (int cc = tid; cc < NC; cc += 128) {
        float a = g2b[cc];
        for (int k = 0; k < GHID; k++) a = fmaf(sh[k], g2w[cc*GHID + k], a);
        g_gate[b*NC + cc] = 1.f / (1.f + expf(-a));
    }
}

// ---------------------------------------------------------------------------
extern "C" void kernel_launch(void* const* d_in, const int* in_sizes, int n_in,
                              void* d_out, int out_size)
{
    const float* x     = (const float*)d_in[0];
    const float* ec1_w = (const float*)d_in[1];
    const float* ec1_b = (const float*)d_in[2];
    const float* bn1_g = (const float*)d_in[3];
    const float* bn1_b = (const float*)d_in[4];
    const float* bn1_m = (const float*)d_in[5];
    const float* bn1_v = (const float*)d_in[6];
    const float* ec2_w = (const float*)d_in[7];
    const float* ec2_b = (const float*)d_in[8];
    const float* bn2_g = (const float*)d_in[9];
    const float* bn2_b = (const float*)d_in[10];
    const float* bn2_m = (const float*)d_in[11];
    const float* bn2_v = (const float*)d_in[12];
    const float* g1_w  = (const float*)d_in[13];
    const float* g1_b  = (const float*)d_in[14];
    const float* gbn_g = (const float*)d_in[15];
    const float* gbn_b = (const float*)d_in[16];
    const float* gbn_m = (const float*)d_in[17];
    const float* gbn_v = (const float*)d_in[18];
    const float* g2_w  = (const float*)d_in[19];
    const float* g2_b  = (const float*)d_in[20];
    const float* out_w = (const float*)d_in[21];
    const float* out_b = (const float*)d_in[22];
    float* out = (float*)d_out;

    const int CONV_SMEM = 10880 * 4;   // 43520 B
    const int OUT_SMEM  = 9088 * 4;    // 36352 B

    wtrans_kernel<<<720, 256>>>(ec1_w, ec2_w);

    conv_mma<NC><<<dim3(32, 16), 128, CONV_SMEM>>>(x, ec1_b, bn1_g, bn1_b, bn1_m, bn1_v);
    conv_mma<CQ><<<dim3(32, 16), 128, CONV_SMEM>>>(x, ec2_b, bn2_g, bn2_b, bn2_m, bn2_v);

    pool_mean_kernel<<<NB*NC, 128>>>(x, 0);
    pool_mean_kernel<<<NB*CQ, 128>>>(x, 1);

    gate_kernel<<<NB, 128>>>(g1_w, g1_b, gbn_g, gbn_b, gbn_m, gbn_v, g2_w, g2_b);

    out_mma<<<dim3(64, 4, NB), 128, OUT_SMEM>>>(x, out_w, out_b, out);
}

// round 9
// speedup vs baseline: 5.4909x; 1.4331x over previous
#include <cuda_runtime.h>
#include <cuda_fp16.h>
#include <math.h>
#include <stdint.h>

#define EPS_BN 1e-5f
#define NB 16
#define NC 256
#define CQ 64
#define GHID 128
#define GIN 320

// ---------------------------------------------------------------------------
// Scratch (allocation-free device globals)
// ---------------------------------------------------------------------------
__device__ __align__(16) uint32_t g_ef1h[NB*32*64*64];  // half2 [b][icpair32][h][w]
__device__ float g_ef2[NB*CQ*64*64];                    // fp32 (pool_e + out_mma)
__device__ float g_xpool[NB*NC];
__device__ float g_epool[NB*CQ];
__device__ float g_gate[NB*NC];
__device__ __align__(16) uint32_t g_w1h[9*64*128];      // half2 [tap][oc][icpair]
__device__ __align__(16) uint32_t g_w2h[9*64*32];

__device__ __forceinline__ uint32_t packh2(float lo, float hi){
    __half2 h = __halves2half2(__float2half_rn(lo), __float2half_rn(hi));
    return *(uint32_t*)&h;
}

// m16n8k16 fp16 MMA, fp32 accum. A row-major, B col-major.
__device__ __forceinline__ void mma16(float* d, const uint32_t* a, const uint32_t* b){
    asm volatile("mma.sync.aligned.m16n8k16.row.col.f32.f16.f16.f32 "
        "{%0,%1,%2,%3}, {%4,%5,%6,%7}, {%8,%9}, {%0,%1,%2,%3};"
        : "+f"(d[0]), "+f"(d[1]), "+f"(d[2]), "+f"(d[3])
        : "r"(a[0]), "r"(a[1]), "r"(a[2]), "r"(a[3]), "r"(b[0]), "r"(b[1]));
}

// ---------------------------------------------------------------------------
// Weight transform: [oc][ic][3][3] fp32 -> [tap][oc][icpair] half2
// ---------------------------------------------------------------------------
__global__ void wtrans_kernel(const float* __restrict__ w1, const float* __restrict__ w2)
{
    int i = blockIdx.x * 256 + threadIdx.x;
    if (i < 9*64*128) {
        int tap = i / (64*128); int rem = i - tap*(64*128);
        int oc = rem >> 7, ip = rem & 127;
        g_w1h[i] = packh2(w1[(oc*256 + 2*ip)*9 + tap], w1[(oc*256 + 2*ip + 1)*9 + tap]);
    }
    int j = i - 9*64*128;
    if (j >= 0 && j < 9*64*32) {
        int tap = j / (64*32); int rem = j - tap*(64*32);
        int oc = rem >> 5, ip = rem & 31;
        g_w2h[j] = packh2(w2[(oc*64 + 2*ip)*9 + tap], w2[(oc*64 + 2*ip + 1)*9 + tap]);
    }
}

// ---------------------------------------------------------------------------
// conv3x3 + BN + ReLU via mma.sync fp16 tap-split implicit GEMM.
// Block: 128 px (2 rows x 64 w) x 64 oc. 4 warps, warp tile 64px x 32oc.
// Grid: (32 rowpairs, 16 batches). Dynamic SMEM: 34304 B.
// SMEM u32 words: slab[ip16][264] @0 (4224), Bs 2 bufs [oc64][20] @4224 (2560),
//                 sinv fp32 @8448, sbeta @8512. sD fp32 [oc64][px132] overlays @0.
// ---------------------------------------------------------------------------
template<int CIN>
__global__ __launch_bounds__(128)
void conv_mma(const float* __restrict__ xg,
              const float* __restrict__ cb,
              const float* __restrict__ bg, const float* __restrict__ bb,
              const float* __restrict__ bm, const float* __restrict__ bv)
{
    extern __shared__ uint32_t smu[];
    uint32_t* slab = smu;                         // 4224
    uint32_t* Bs   = smu + 4224;                  // 2x1280
    float* sinv    = (float*)(smu + 8448);        // 64
    float* sbeta   = (float*)(smu + 8512);        // 64

    float* __restrict__ outp      = (CIN == NC) ? nullptr : (float*)g_ef2;
    const uint32_t* __restrict__ wth = (CIN == NC) ? (const uint32_t*)g_w1h : (const uint32_t*)g_w2h;
    const int IPC = CIN / 2;   // icpairs per oc row in weight tensor

    const int tid = threadIdx.x, lane = tid & 31, wid = tid >> 5;
    const int warpM = wid & 1, warpN = wid >> 1;     // M: 2x64px, N: 2x32oc
    const int r = lane >> 2, c = lane & 3;
    const int b = blockIdx.y, h0 = blockIdx.x * 2;

    if (tid < 64) {
        float inv = bg[tid] * rsqrtf(bv[tid] + EPS_BN);
        sinv[tid]  = inv;
        sbeta[tid] = (cb[tid] - bm[tid]) * inv + bb[tid];
    }
    // halo columns (ws=0, ws=65) always zero: 16 ip * 4 rs * 2
    if (tid < 128) {
        int ip = tid >> 3, rem = tid & 7, rs = rem >> 1, e = rem & 1;
        slab[ip*264 + rs*66 + e*65] = 0u;
    }

    float d[4][4][4];
    #pragma unroll
    for (int mt = 0; mt < 4; mt++)
        #pragma unroll
        for (int nt = 0; nt < 4; nt++)
            #pragma unroll
            for (int q = 0; q < 4; q++) d[mt][nt][q] = 0.f;

    const int CH = CIN / 32;
    for (int ch = 0; ch < CH; ch++) {
        __syncthreads();   // prior readers done with slab
        if (CIN == NC) {
            // pack x fp32 -> half2 pairs
            const float* xs = xg + ((size_t)(b*CIN + ch*32)) * 4096;
            #pragma unroll 4
            for (int i = tid; i < 1024; i += 128) {
                int ip = i >> 6, rem = i & 63, rs = rem >> 4, q = rem & 15;
                int gr = h0 - 1 + rs;
                uint32_t v0 = 0, v1 = 0, v2 = 0, v3 = 0;
                if ((unsigned)gr < 64u) {
                    const float* p0 = xs + (2*ip)*4096 + gr*64 + q*4;
                    float4 a4 = *(const float4*)p0;
                    float4 b4 = *(const float4*)(p0 + 4096);
                    v0 = packh2(a4.x, b4.x); v1 = packh2(a4.y, b4.y);
                    v2 = packh2(a4.z, b4.z); v3 = packh2(a4.w, b4.w);
                }
                uint32_t* dst = slab + ip*264 + rs*66 + 1 + q*4;
                dst[0]=v0; dst[1]=v1; dst[2]=v2; dst[3]=v3;
            }
        } else {
            // ef1 already half2-packed: raw uint4 copy
            const uint32_t* es = g_ef1h + ((size_t)(b*32 + ch*16)) * 4096;
            #pragma unroll 4
            for (int i = tid; i < 1024; i += 128) {
                int ip = i >> 6, rem = i & 63, rs = rem >> 4, q = rem & 15;
                int gr = h0 - 1 + rs;
                uint4 v = make_uint4(0u,0u,0u,0u);
                if ((unsigned)gr < 64u)
                    v = *(const uint4*)(es + ip*4096 + gr*64 + q*4);
                uint32_t* dst = slab + ip*264 + rs*66 + 1 + q*4;
                dst[0]=v.x; dst[1]=v.y; dst[2]=v.z; dst[3]=v.w;
            }
        }

        for (int tap = 0; tap < 9; tap++) {
            const int buf = (ch*9 + tap) & 1;
            // stage B half2 [oc64][icpair16] pad 20 (double-buffered: 1 sync/tap)
            {
                const uint32_t* ws_ = wth + ((size_t)tap*64)*IPC + ch*16;
                #pragma unroll
                for (int i = tid; i < 256; i += 128) {
                    int oc = i >> 2, iq = i & 3;
                    *(uint4*)(Bs + buf*1280 + oc*20 + iq*4) =
                        *(const uint4*)(ws_ + oc*IPC + iq*4);
                }
            }
            __syncthreads();
            const int kh = tap / 3, kw = tap - kh*3;
            const int rowoff = (warpM + kh)*66 + kw;
            const uint32_t* Bb = Bs + buf*1280;

            #pragma unroll
            for (int s = 0; s < 2; s++) {
                const int ip0 = s*8 + c;
                uint32_t a[4][4];
                #pragma unroll
                for (int mt = 0; mt < 4; mt++) {
                    int ws = rowoff + mt*16 + r;
                    a[mt][0] = slab[ip0*264 + ws];
                    a[mt][1] = slab[ip0*264 + ws + 8];
                    a[mt][2] = slab[(ip0+4)*264 + ws];
                    a[mt][3] = slab[(ip0+4)*264 + ws + 8];
                }
                uint32_t bf[4][2];
                #pragma unroll
                for (int nt = 0; nt < 4; nt++) {
                    int oc = warpN*32 + nt*8 + r;
                    bf[nt][0] = Bb[oc*20 + ip0];
                    bf[nt][1] = Bb[oc*20 + ip0 + 4];
                }
                #pragma unroll
                for (int mt = 0; mt < 4; mt++)
                    #pragma unroll
                    for (int nt = 0; nt < 4; nt++)
                        mma16(d[mt][nt], a[mt], bf[nt]);
            }
        }
    }

    // Epilogue: BN+ReLU, transpose through smem, vectorized store
    __syncthreads();
    float* sD = (float*)smu;   // [oc64][px132] = 8448 fl (sinv/sbeta live above)
    #pragma unroll
    for (int mt = 0; mt < 4; mt++) {
        int px0 = warpM*64 + mt*16 + r;
        #pragma unroll
        for (int nt = 0; nt < 4; nt++) {
            int oc0 = warpN*32 + nt*8 + c*2;
            float i0 = sinv[oc0],   b0 = sbeta[oc0];
            float i1 = sinv[oc0+1], b1 = sbeta[oc0+1];
            float v0 = d[mt][nt][0]*i0 + b0;
            float v1 = d[mt][nt][1]*i1 + b1;
            float v2 = d[mt][nt][2]*i0 + b0;
            float v3 = d[mt][nt][3]*i1 + b1;
            sD[oc0*132 + px0]           = v0 > 0.f ? v0 : 0.f;
            sD[(oc0+1)*132 + px0]       = v1 > 0.f ? v1 : 0.f;
            sD[oc0*132 + px0 + 8]       = v2 > 0.f ? v2 : 0.f;
            sD[(oc0+1)*132 + px0 + 8]   = v3 > 0.f ? v3 : 0.f;
        }
    }
    __syncthreads();
    if (CIN == NC) {
        // pack oc pairs -> g_ef1h half2 [b][ocpair32][h][w]
        #pragma unroll 4
        for (int i = tid; i < 1024; i += 128) {
            int op = i >> 5, pxq = i & 31;
            int px = pxq * 4, rs = px >> 6, w = px & 63;
            const float* r0 = sD + (2*op)*132 + px;
            const float* r1 = sD + (2*op+1)*132 + px;
            uint4 v;
            v.x = packh2(r0[0], r1[0]); v.y = packh2(r0[1], r1[1]);
            v.z = packh2(r0[2], r1[2]); v.w = packh2(r0[3], r1[3]);
            *(uint4*)(g_ef1h + ((size_t)(b*32 + op)*64 + h0 + rs)*64 + w) = v;
        }
    } else {
        #pragma unroll 4
        for (int i = tid; i < 2048; i += 128) {
            int oc = i >> 5, pxq = i & 31;
            int px = pxq * 4, rs = px >> 6, w = px & 63;
            float4 v = *(const float4*)(sD + oc*132 + px);
            *(float4*)(outp + (((size_t)b*64 + oc)*64 + h0 + rs)*64 + w) = v;
        }
    }
}

// ---------------------------------------------------------------------------
// Output 1x1 GEMM + gated residual, fp16 MMA. Block 64px x 64oc, 4 warps.
// Grid: (64 h, 4 oc-chunks, 16 b). SMEM: 18944 B.
// u32 words: sAh[ip32][72] @0 (2304), sBh[oc64][36] @2304 (2304),
//            sgate @4608, sob @4672. sD fp32 [oc64][w68] overlays @0.
// ---------------------------------------------------------------------------
__global__ __launch_bounds__(128)
void out_mma(const float* __restrict__ x, const float* __restrict__ ow,
             const float* __restrict__ ob, float* __restrict__ out)
{
    extern __shared__ uint32_t smu[];
    uint32_t* sAh  = smu;            // 2304
    uint32_t* sBh  = smu + 2304;     // 2304
    float* sgate   = (float*)(smu + 4608);
    float* sob     = (float*)(smu + 4672);

    const int tid = threadIdx.x, lane = tid & 31, warpN = tid >> 5;
    const int r = lane >> 2, c = lane & 3;
    const int h = blockIdx.x, och = blockIdx.y, b = blockIdx.z;
    const int ocb = och * 64;

    if (tid < 64) {
        sgate[tid] = g_gate[b*256 + ocb + tid];
        sob[tid]   = ob[ocb + tid];
    }
    // A: pack ef2 fp32 -> half2 [ip32][w]
    #pragma unroll
    for (int i = tid; i < 512; i += 128) {
        int ip = i >> 4, wq = i & 15;
        const float* p0 = g_ef2 + (((size_t)b*64 + 2*ip)*64 + h)*64 + wq*4;
        float4 a4 = *(const float4*)p0;
        float4 b4 = *(const float4*)(p0 + 4096);
        uint4 v;
        v.x = packh2(a4.x, b4.x); v.y = packh2(a4.y, b4.y);
        v.z = packh2(a4.z, b4.z); v.w = packh2(a4.w, b4.w);
        *(uint4*)(sAh + ip*72 + wq*4) = v;
    }
    // B: pack out_w fp32 -> half2 [oc64][ip32] pad 36
    #pragma unroll
    for (int i = tid; i < 1024; i += 128) {
        int oc = i >> 4, q = i & 15;
        float4 wv = *(const float4*)(ow + (ocb + oc)*64 + q*4);
        uint32_t* dst = sBh + oc*36 + q*2;
        dst[0] = packh2(wv.x, wv.y);
        dst[1] = packh2(wv.z, wv.w);
    }
    __syncthreads();

    float d[4][2][4];
    #pragma unroll
    for (int mt = 0; mt < 4; mt++)
        #pragma unroll
        for (int nt = 0; nt < 2; nt++)
            #pragma unroll
            for (int q = 0; q < 4; q++) d[mt][nt][q] = 0.f;

    #pragma unroll
    for (int s = 0; s < 4; s++) {
        const int ip0 = s*8 + c;
        uint32_t a[4][4];
        #pragma unroll
        for (int mt = 0; mt < 4; mt++) {
            int ws = mt*16 + r;
            a[mt][0] = sAh[ip0*72 + ws];
            a[mt][1] = sAh[ip0*72 + ws + 8];
            a[mt][2] = sAh[(ip0+4)*72 + ws];
            a[mt][3] = sAh[(ip0+4)*72 + ws + 8];
        }
        uint32_t bf[2][2];
        #pragma unroll
        for (int nt = 0; nt < 2; nt++) {
            int oc = warpN*16 + nt*8 + r;
            bf[nt][0] = sBh[oc*36 + ip0];
            bf[nt][1] = sBh[oc*36 + ip0 + 4];
        }
        #pragma unroll
        for (int mt = 0; mt < 4; mt++)
            #pragma unroll
            for (int nt = 0; nt < 2; nt++)
                mma16(d[mt][nt], a[mt], bf[nt]);
    }

    __syncthreads();
    float* sD = (float*)smu;   // [oc64][w68] = 4352 fl (sgate/sob live above)
    #pragma unroll
    for (int mt = 0; mt < 4; mt++) {
        int px0 = mt*16 + r;
        #pragma unroll
        for (int nt = 0; nt < 2; nt++) {
            int oc0 = warpN*16 + nt*8 + c*2;
            sD[oc0*68 + px0]         = d[mt][nt][0];
            sD[(oc0+1)*68 + px0]     = d[mt][nt][1];
            sD[oc0*68 + px0 + 8]     = d[mt][nt][2];
            sD[(oc0+1)*68 + px0 + 8] = d[mt][nt][3];
        }
    }
    __syncthreads();
    #pragma unroll
    for (int i = tid; i < 1024; i += 128) {
        int oc = i >> 4, wq = i & 15;
        size_t idx = (((size_t)b*256 + ocb + oc)*64 + h)*64 + wq*4;
        float4 xv = *(const float4*)(x + idx);
        float4 dv = *(const float4*)(sD + oc*68 + wq*4);
        float g = sgate[oc], o = sob[oc];
        float4 rv;
        rv.x = xv.x + g*(dv.x + o);
        rv.y = xv.y + g*(dv.y + o);
        rv.z = xv.z + g*(dv.z + o);
        rv.w = xv.w + g*(dv.w + o);
        *(float4*)(out + idx) = rv;
    }
}

// ---------------------------------------------------------------------------
// Per-(b,c) spatial mean: 256 threads, float4, MLP-4
// ---------------------------------------------------------------------------
__global__ __launch_bounds__(256)
void pool_mean_kernel(const float* __restrict__ xext, int which)
{
    const float* src = (which == 0) ? xext : (const float*)g_ef2;
    float* dst       = (which == 0) ? g_xpool : g_epool;
    int bc = blockIdx.x, tid = threadIdx.x;
    const float4* p = (const float4*)(src + (size_t)bc * 4096);
    float4 acc[4];
    #pragma unroll
    for (int j = 0; j < 4; j++) acc[j] = p[tid + j*256];
    float s = 0.f;
    #pragma unroll
    for (int j = 0; j < 4; j++) s += (acc[j].x + acc[j].y) + (acc[j].z + acc[j].w);
    __shared__ float red[8];
    #pragma unroll
    for (int o = 16; o > 0; o >>= 1) s += __shfl_down_sync(0xffffffffu, s, o);
    if ((tid & 31) == 0) red[tid >> 5] = s;
    __syncthreads();
    if (tid == 0) {
        float t = 0.f;
        #pragma unroll
        for (int i = 0; i < 8; i++) t += red[i];
        dst[bc] = t * (1.f / 4096.f);
    }
}

// ---------------------------------------------------------------------------
// Gate MLP
// ---------------------------------------------------------------------------
__global__ void gate_kernel(const float* __restrict__ g1w, const float* __restrict__ g1b,
                            const float* __restrict__ gg,  const float* __restrict__ gb2,
                            const float* __restrict__ gm,  const float* __restrict__ gv,
                            const float* __restrict__ g2w, const float* __restrict__ g2b)
{
    __shared__ float sg[GIN];
    __shared__ float sh[GHID];
    int b = blockIdx.x, tid = threadIdx.x;
    for (int i = tid; i < NC; i += 128) sg[i] = g_xpool[b*NC + i];
    if (tid < CQ) sg[NC + tid] = g_epool[b*CQ + tid];
    __syncthreads();
    {
        int j = tid;
        float a = g1b[j];
        for (int k = 0; k < GIN; k++) a = fmaf(sg[k], g1w[j*GIN + k], a);
        float inv = gg[j] * rsqrtf(gv[j] + EPS_BN);
        a = (a - gm[j]) * inv + gb2[j];
        sh[j] = a > 0.f ? a : 0.f;
    }
    __syncthreads();
    for (int cc = tid; cc < NC; cc += 128) {
        float a = g2b[cc];
        for (int k = 0; k < GHID; k++) a = fmaf(sh[k], g2w[cc*GHID + k], a);
        g_gate[b*NC + cc] = 1.f / (1.f + expf(-a));
    }
}

// ---------------------------------------------------------------------------
extern "C" void kernel_launch(void* const* d_in, const int* in_sizes, int n_in,
                              void* d_out, int out_size)
{
    const float* x     = (const float*)d_in[0];
    const float* ec1_w = (const float*)d_in[1];
    const float* ec1_b = (const float*)d_in[2];
    const float* bn1_g = (const float*)d_in[3];
    const float* bn1_b = (const float*)d_in[4];
    const float* bn1_m = (const float*)d_in[5];
    const float* bn1_v = (const float*)d_in[6];
    const float* ec2_w = (const float*)d_in[7];
    const float* ec2_b = (const float*)d_in[8];
    const float* bn2_g = (const float*)d_in[9];
    const float* bn2_b = (const float*)d_in[10];
    const float* bn2_m = (const float*)d_in[11];
    const float* bn2_v = (const float*)d_in[12];
    const float* g1_w  = (const float*)d_in[13];
    const float* g1_b  = (const float*)d_in[14];
    const float* gbn_g = (const float*)d_in[15];
    const float* gbn_b = (const float*)d_in[16];
    const float* gbn_m = (const float*)d_in[17];
    const float* gbn_v = (const float*)d_in[18];
    const float* g2_w  = (const float*)d_in[19];
    const float* g2_b  = (const float*)d_in[20];
    const float* out_w = (const float*)d_in[21];
    const float* out_b = (const float*)d_in[22];
    float* out = (float*)d_out;

    const int CONV_SMEM = 34304;   // B (< 48KB)
    const int OUT_SMEM  = 18944;   // B (< 48KB)

    wtrans_kernel<<<360, 256>>>(ec1_w, ec2_w);

    conv_mma<NC><<<dim3(32, 16), 128, CONV_SMEM>>>(x, ec1_b, bn1_g, bn1_b, bn1_m, bn1_v);
    conv_mma<CQ><<<dim3(32, 16), 128, CONV_SMEM>>>(x, ec2_b, bn2_g, bn2_b, bn2_m, bn2_v);

    pool_mean_kernel<<<NB*NC, 256>>>(x, 0);
    pool_mean_kernel<<<NB*CQ, 256>>>(x, 1);

    gate_kernel<<<NB, 128>>>(g1_w, g1_b, gbn_g, gbn_b, gbn_m, gbn_v, g2_w, g2_b);

    out_mma<<<dim3(64, 4, NB), 128, OUT_SMEM>>>(x, out_w, out_b, out);
}